// round 14
// baseline (speedup 1.0000x reference)
#include <cuda_runtime.h>
#include <cuda_fp16.h>
#include <math.h>

// ---------------- problem constants ----------------
#define BATCH   4096
#define C1      64
#define IMH     28
#define IMW     28
#define PH      12
#define POS     (PH*PH)         // 144
#define CL      (C1*POS)        // 9216
#define NFC     1024
#define K1K     400
#define KFC     100
#define CAP     512
#define CANDCAP 128
#define CAND1   512

// K1 dynamic smem layout (bytes)
#define OFF_PATCH 0                    // 576 rows x 80 B fp16 patches
#define OFF_WB    46080                // 64 rows x 80 B fp16 weights
#define OFF_KEYS  51200                // 9216 u32 keys
#define OFF_IMG   88064                // 784 f32
#define K1_DSM    91200

// ---------------- scratch (static device globals) ----------------
__device__ __align__(16) __half g_Wh[CL * NFC];       // masked fc1_w^T fp16, 18.9 MB
__device__ __align__(16) float2 g_pair[BATCH * CAP];  // {val, as_float(j*256)}
__device__ int            g_cnt[BATCH];

// order-preserving float <-> uint transforms
__device__ __forceinline__ unsigned int f2u(float f) {
    unsigned int u = __float_as_uint(f);
    return (u & 0x80000000u) ? ~u : (u | 0x80000000u);
}
__device__ __forceinline__ float u2f(unsigned int u) {
    unsigned int b = (u & 0x80000000u) ? (u & 0x7fffffffu) : ~u;
    return __uint_as_float(b);
}
__device__ __forceinline__ unsigned int smem_u32(const void* p) {
    unsigned int a;
    asm("{ .reg .u64 t; cvta.to.shared.u64 t, %1; cvt.u32.u64 %0, t; }"
        : "=r"(a) : "l"(p));
    return a;
}
__device__ __forceinline__ void ldsm4(unsigned int& x0, unsigned int& x1,
                                      unsigned int& x2, unsigned int& x3,
                                      unsigned int addr) {
    asm volatile("ldmatrix.sync.aligned.m8n8.x4.shared.b16 {%0,%1,%2,%3}, [%4];"
                 : "=r"(x0), "=r"(x1), "=r"(x2), "=r"(x3) : "r"(addr));
}
__device__ __forceinline__ void ldsm2(unsigned int& x0, unsigned int& x1,
                                      unsigned int addr) {
    asm volatile("ldmatrix.sync.aligned.m8n8.x2.shared.b16 {%0,%1}, [%2];"
                 : "=r"(x0), "=r"(x1) : "r"(addr));
}
__device__ __forceinline__ void mma16816(float& d0, float& d1, float& d2, float& d3,
                                         unsigned int a0, unsigned int a1,
                                         unsigned int a2, unsigned int a3,
                                         unsigned int b0, unsigned int b1) {
    asm volatile(
        "mma.sync.aligned.m16n8k16.row.col.f32.f16.f16.f32 "
        "{%0,%1,%2,%3}, {%4,%5,%6,%7}, {%8,%9}, {%0,%1,%2,%3};"
        : "+f"(d0), "+f"(d1), "+f"(d2), "+f"(d3)
        : "r"(a0), "r"(a1), "r"(a2), "r"(a3), "r"(b0), "r"(b1));
}

// warp-parallel exact bin selection over hist[256]
__device__ __forceinline__ void warp_select_bin(
    const unsigned int* hist, int kk, int lane, int shift, unsigned int pfx,
    volatile unsigned int* sel_prefix, volatile int* sel_kr)
{
    int base = 255 - lane * 8;
    unsigned int hb[8];
    unsigned int s = 0;
#pragma unroll
    for (int q = 0; q < 8; q++) { hb[q] = hist[base - q]; s += hb[q]; }
    unsigned int incl = s;
#pragma unroll
    for (int d = 1; d < 32; d <<= 1) {
        unsigned int t = __shfl_up_sync(0xFFFFFFFFu, incl, d);
        if (lane >= d) incl += t;
    }
    unsigned int excl = incl - s;
    if (excl < (unsigned)kk && (unsigned)kk <= incl) {
        unsigned int acc = excl;
#pragma unroll
        for (int q = 0; q < 8; q++) {
            if (acc + hb[q] >= (unsigned)kk) {
                *sel_prefix = pfx | ((unsigned)(base - q) << shift);
                *sel_kr = kk - (int)acc;
                break;
            }
            acc += hb[q];
        }
    }
}

// exact fp32 pooled conv value (incl. bias) for flat index i
__device__ __forceinline__ float exact_pooled(const float* img, const float* wts,
                                              const float* bias, int i) {
    int c = i / POS, pos = i - c * POS;
    int py = pos / PH, px = pos - py * PH;
    const float* wc = wts + c * 25;
    float m = -1e30f;
#pragma unroll
    for (int q = 0; q < 4; q++) {
        int r0 = py * 2 + (q >> 1), c0 = px * 2 + (q & 1);
        float s = 0.f;
#pragma unroll
        for (int u = 0; u < 5; u++)
#pragma unroll
            for (int v = 0; v < 5; v++)
                s = fmaf(img[(r0 + u) * IMW + c0 + v], wc[u * 5 + v], s);
        m = fmaxf(m, s);
    }
    return m + bias[c];
}

// ================= K0: mask + transpose + fp16-convert fc1 weights ============
__global__ void k_prep(const float* __restrict__ w, const float* __restrict__ m) {
    __shared__ float tile[32][33];
    int jb = blockIdx.x * 32;
    int nb = blockIdx.y * 32;
    int tx = threadIdx.x, ty = threadIdx.y;   // (32, 8)
#pragma unroll
    for (int r = 0; r < 32; r += 8) {
        int n = nb + ty + r;
        int j = jb + tx;
        float wv = w[n * CL + j];
        float mv = m[n * CL + j];
        tile[ty + r][tx] = (mv < 0.5f) ? wv : 0.0f;
    }
    __syncthreads();
#pragma unroll
    for (int r = 0; r < 32; r += 8) {
        int j = jb + ty + r;
        int n = nb + tx;
        g_Wh[j * NFC + n] = __float2half(tile[tx][ty + r]);
    }
}

// ================= K1: HMMA conv + pool + repaired kwinners(400/9216) =========
#define T1 288

__global__ void __launch_bounds__(T1, 2) k_conv_pool_kw(
    const float* __restrict__ x, const float* __restrict__ cw,
    const float* __restrict__ cb, const float* __restrict__ duty)
{
    extern __shared__ unsigned char dysm[];
    __half*        patches = (__half*)(dysm + OFF_PATCH);   // [576][40] halfs
    __half*        wtsB    = (__half*)(dysm + OFF_WB);      // [64][40] halfs
    unsigned int*  s_keys  = (unsigned int*)(dysm + OFF_KEYS);
    float*         img     = (float*)(dysm + OFF_IMG);

    __shared__ float wts[C1 * 25];
    __shared__ float bias[C1];
    __shared__ float boost[C1];
    __shared__ float s_Ac[C1];
    __shared__ unsigned int hist[256];
    __shared__ int s_wsum[9];
    __shared__ float s_pm[9];
    __shared__ unsigned int sel_prefix;
    __shared__ int sel_kr;
    __shared__ int sel_total;
    __shared__ int s_ic9[9];
    __shared__ int s_ccnt;
    __shared__ int s_cnd_i[CAND1];
    __shared__ unsigned int s_cnd_k[CAND1];
    __shared__ float s_P;

    const int tid  = threadIdx.x;
    const int b    = blockIdx.x;
    const int lane = tid & 31, wrp = tid >> 5;

    // ---- load img (track max|.|), conv weights; derived constants ----
    const float* xb = x + b * (IMH * IMW);
    float pm = 0.f;
    for (int i = tid; i < IMH * IMW; i += T1) {
        float v = xb[i];
        img[i] = v;
        pm = fmaxf(pm, fabsf(v));
    }
#pragma unroll
    for (int d = 16; d > 0; d >>= 1)
        pm = fmaxf(pm, __shfl_down_sync(0xFFFFFFFFu, pm, d));
    if (lane == 0) s_pm[wrp] = pm;
    for (int i = tid; i < C1 * 25; i += T1) wts[i] = cw[i];
    if (tid == 0) s_ccnt = 0;
    __syncthreads();
    if (tid < C1) {
        bias[tid]  = cb[tid];
        boost[tid] = expf(400.0f / 9216.0f - duty[tid]);
        float a = 0.f;
        for (int k = 0; k < 25; k++) a += fabsf(wts[tid * 25 + k]);
        s_Ac[tid] = a;
    }
    if (tid == 0) {
        float P = 0.f;
        for (int w = 0; w < 9; w++) P = fmaxf(P, s_pm[w]);
        s_P = P;
    }
    __syncthreads();
    const float P = s_P;

    // ---- im2col: patches[m][k], m = pooled_pos*4 + quadrant ----
    for (int e = tid; e < 576 * 25; e += T1) {
        int m = e / 25, k = e - m * 25;
        int pp = m >> 2, q = m & 3;
        int py = pp / PH, px = pp - py * PH;
        int r0 = py * 2 + (q >> 1), c0 = px * 2 + (q & 1);
        int u = k / 5, v = k - u * 5;
        patches[m * 40 + k] = __float2half(img[(r0 + u) * IMW + c0 + v]);
    }
    for (int e = tid; e < 576 * 7; e += T1) {
        int m = e / 7, r = e - m * 7;
        patches[m * 40 + 25 + r] = __float2half(0.f);
    }
    for (int e = tid; e < C1 * 25; e += T1) {
        int n = e / 25, k = e - n * 25;
        wtsB[n * 40 + k] = __float2half(wts[e]);
    }
    for (int e = tid; e < C1 * 7; e += T1) {
        int n = e / 7, r = e - n * 7;
        wtsB[n * 40 + 25 + r] = __float2half(0.f);
    }
    __syncthreads();

    // ---- HMMA conv + pooling ----
    {
        const unsigned int pA = smem_u32(patches);
        const unsigned int pB = smem_u32(wtsB);
        const int g = lane >> 3;
        const int arow_ = (lane & 7) + ((g & 1) << 3);
        const int acadd = g >> 1;
        const int brow_ = lane & 7;
        const int bcadd = (lane >> 3) & 1;
        const int rg = lane >> 2;

        for (int t = wrp * 32; t < wrp * 32 + 32; t++) {
            int mt = t >> 3, nt = t & 7;
            int m0 = mt * 16, n0 = nt * 8;
            float d0 = 0.f, d1 = 0.f, d2 = 0.f, d3 = 0.f;
#pragma unroll
            for (int kk = 0; kk < 2; kk++) {
                unsigned int a0, a1, a2, a3, b0, b1;
                ldsm4(a0, a1, a2, a3,
                      pA + (m0 + arow_) * 80 + (2 * kk + acadd) * 16);
                ldsm2(b0, b1,
                      pB + (n0 + brow_) * 80 + (2 * kk + bcadd) * 16);
                mma16816(d0, d1, d2, d3, a0, a1, a2, a3, b0, b1);
            }
            // maxpool across 4-row groups (rows = conv quadrants)
#pragma unroll
            for (int d = 4; d <= 8; d <<= 1) {
                d0 = fmaxf(d0, __shfl_xor_sync(0xFFFFFFFFu, d0, d));
                d1 = fmaxf(d1, __shfl_xor_sync(0xFFFFFFFFu, d1, d));
                d2 = fmaxf(d2, __shfl_xor_sync(0xFFFFFFFFu, d2, d));
                d3 = fmaxf(d3, __shfl_xor_sync(0xFFFFFFFFu, d3, d));
            }
            if (rg == 0 || rg == 4) {
                int ppb = mt * 4 + (rg >> 2);      // pooled row (d0/d1)
                int c0i = n0 + (lane & 3) * 2;
                float v;
                v = d0 + bias[c0i];
                s_keys[c0i * POS + ppb] = f2u(v * boost[c0i]);
                v = d1 + bias[c0i + 1];
                s_keys[(c0i + 1) * POS + ppb] = f2u(v * boost[c0i + 1]);
                v = d2 + bias[c0i];
                s_keys[c0i * POS + ppb + 2] = f2u(v * boost[c0i]);
                v = d3 + bias[c0i + 1];
                s_keys[(c0i + 1) * POS + ppb + 2] = f2u(v * boost[c0i + 1]);
            }
        }
    }
    __syncthreads();

    // ---- radix select approx rank-400 threshold ----
    if (tid == 0) { sel_prefix = 0u; sel_kr = K1K; }
    __syncthreads();
    for (int shift = 24; shift >= 0; shift -= 8) {
        if (tid < 256) hist[tid] = 0u;
        __syncthreads();
        unsigned int pfx    = sel_prefix;
        int          kk     = sel_kr;
        unsigned int himask = (shift == 24) ? 0u : (0xFFFFFFFFu << (shift + 8));
        for (int i = tid; i < CL; i += T1) {
            unsigned int u = s_keys[i];
            if ((u & himask) == pfx) atomicAdd(&hist[(u >> shift) & 255], 1u);
        }
        __syncthreads();
        if (wrp == 0)
            warp_select_bin(hist, kk, lane, shift, pfx, &sel_prefix, &sel_kr);
        __syncthreads();
    }
    const unsigned int thr = sel_prefix;
    const float tval = u2f(thr);

    // ---- flag pass: count definite-ins, collect boundary candidates ----
    const float bconst = 2.5f * 9.765625e-4f * P;   // 2.5 * 2^-10 * P
    int myic = 0;
    for (int i = tid; i < CL; i += T1) {
        unsigned int k = s_keys[i];
        int c = i / POS;
        float band = bconst * s_Ac[c] * boost[c];
        bool cand = fabsf(u2f(k) - tval) <= band;
        if (cand) {
            int pos = atomicAdd(&s_ccnt, 1);
            if (pos < CAND1) s_cnd_i[pos] = i;
        } else if (k >= thr) {
            myic++;
        }
    }
#pragma unroll
    for (int d = 16; d > 0; d >>= 1) myic += __shfl_down_sync(0xFFFFFFFFu, myic, d);
    if (lane == 0) s_ic9[wrp] = myic;
    __syncthreads();
    int ccnt = min(s_ccnt, CAND1);

    // ---- exact fp32 recompute for candidate keys ----
    for (int c = tid; c < ccnt; c += T1) {
        int i = s_cnd_i[c];
        float ex = exact_pooled(img, wts, bias, i);
        s_cnd_k[c] = f2u(ex * boost[i / POS]);
    }
    __syncthreads();

    // ---- resolve candidates exactly (count-based, >= kth tie semantics) ----
    int ic = 0;
#pragma unroll
    for (int w = 0; w < 9; w++) ic += s_ic9[w];
    int r = K1K - ic;
    if (r < 0) r = 0;
    if (s_ccnt <= CAND1) {
        for (int c = tid; c < ccnt; c += T1) {
            unsigned int kc = s_cnd_k[c];
            int cg = 0;
            for (int d = 0; d < ccnt; d++) cg += (s_cnd_k[d] > kc);
            s_keys[s_cnd_i[c]] = (cg < r) ? 0xFFFFFFFFu : 0u;
        }
    }
    __syncthreads();

    // ---- deterministic compaction with exact fp32 value recompute ----
    int mycnt = 0;
    for (int i = tid; i < CL; i += T1)
        if (s_keys[i] >= thr) mycnt++;

    int v = mycnt;
#pragma unroll
    for (int d = 1; d < 32; d <<= 1) {
        int t = __shfl_up_sync(0xFFFFFFFFu, v, d);
        if (lane >= d) v += t;
    }
    if (lane == 31) s_wsum[wrp] = v;
    __syncthreads();
    if (tid == 0) {
        int a = 0;
        for (int w = 0; w < 9; w++) { int t = s_wsum[w]; s_wsum[w] = a; a += t; }
        sel_total = a;
    }
    __syncthreads();
    int off = s_wsum[wrp] + v - mycnt;
    for (int i = tid; i < CL; i += T1) {
        if (s_keys[i] >= thr) {
            if (off < CAP) {
                float ev = exact_pooled(img, wts, bias, i);
                g_pair[b * CAP + off] =
                    make_float2(ev, __int_as_float(i << 8));   // j * (NFC/4)
            }
            off++;
        }
    }
    if (tid == 0) g_cnt[b] = sel_total > CAP ? CAP : sel_total;
}

// ================= K2: fp16 fc1 + exact-boundary kwinners + fc2 + lsm =========
#define T2 256

__global__ void __launch_bounds__(T2) k_fc_out(
    const float* __restrict__ fw,    const float* __restrict__ fmask,
    const float* __restrict__ fc1_b, const float* __restrict__ duty_fc,
    const float* __restrict__ w2,    const float* __restrict__ b2,
    float* __restrict__ out)
{
    __shared__ float2        s_pair[CAP];
    __shared__ float         s_h[NFC];
    __shared__ float         s_bst[NFC];
    __shared__ unsigned int  s_keys[NFC];
    __shared__ unsigned char s_flag[NFC];
    __shared__ unsigned int  hist[256];
    __shared__ unsigned int  sel_prefix;
    __shared__ int           sel_kr;
    __shared__ float         s_red[8][10];
    __shared__ float         s_logits[10];
    __shared__ float         s_lse;
    __shared__ float         s_Q[8];
    __shared__ int           s_ic[8];
    __shared__ int           s_ccnt;
    __shared__ int           s_cnd_n[CANDCAP];
    __shared__ unsigned int  s_cnd_k[CANDCAP];
    __shared__ unsigned char s_used[CANDCAP];

    const int tid  = threadIdx.x;
    const int b    = blockIdx.x;
    const int lane = tid & 31, wrp = tid >> 5;

    int cnt = g_cnt[b];
    float myQ = 0.f;
    for (int i = tid; i < cnt; i += T2) {
        float2 pr = g_pair[b * CAP + i];
        s_pair[i] = pr;
        myQ = fmaf(pr.x, pr.x, myQ);
    }
#pragma unroll
    for (int d = 16; d > 0; d >>= 1) myQ += __shfl_down_sync(0xFFFFFFFFu, myQ, d);
    if (lane == 0) s_Q[wrp] = myQ;
    if (tid == 0) s_ccnt = 0;
    __syncthreads();
    float Q2 = 0.f;
#pragma unroll
    for (int w = 0; w < 8; w++) Q2 += s_Q[w];

    // ---- fp16 sparse accumulate ----
    float a0 = 0.f, a1 = 0.f, a2 = 0.f, a3 = 0.f;
    const uint2* __restrict__ W8 = (const uint2*)g_Wh;
#pragma unroll 8
    for (int e = 0; e < cnt; e++) {
        float2 pv = s_pair[e];
        int jn = __float_as_int(pv.y);
        uint2 wraw = __ldg(&W8[jn + tid]);
        float2 f01 = __half22float2(*(const __half2*)&wraw.x);
        float2 f23 = __half22float2(*(const __half2*)&wraw.y);
        a0 = fmaf(pv.x, f01.x, a0);
        a1 = fmaf(pv.x, f01.y, a1);
        a2 = fmaf(pv.x, f23.x, a2);
        a3 = fmaf(pv.x, f23.y, a3);
    }

    const float kdn = 100.0f / 1024.0f;
    {
        int n = tid * 4;
        float h0 = a0 + fc1_b[n],     h1 = a1 + fc1_b[n + 1];
        float h2 = a2 + fc1_b[n + 2], h3 = a3 + fc1_b[n + 3];
        float b0 = expf(kdn - duty_fc[n]),      b1 = expf(kdn - duty_fc[n + 1]);
        float b2v = expf(kdn - duty_fc[n + 2]), b3 = expf(kdn - duty_fc[n + 3]);
        s_h[n] = h0; s_h[n+1] = h1; s_h[n+2] = h2; s_h[n+3] = h3;
        s_bst[n] = b0; s_bst[n+1] = b1; s_bst[n+2] = b2v; s_bst[n+3] = b3;
        s_keys[n]   = f2u(h0 * b0);
        s_keys[n+1] = f2u(h1 * b1);
        s_keys[n+2] = f2u(h2 * b2v);
        s_keys[n+3] = f2u(h3 * b3);
    }
    __syncthreads();

    // ---- radix select approx rank-100 threshold ----
    if (tid == 0) { sel_prefix = 0u; sel_kr = KFC; }
    __syncthreads();
    for (int shift = 24; shift >= 0; shift -= 8) {
        hist[tid] = 0u;
        __syncthreads();
        unsigned int pfx    = sel_prefix;
        int          kk     = sel_kr;
        unsigned int himask = (shift == 24) ? 0u : (0xFFFFFFFFu << (shift + 8));
#pragma unroll
        for (int q = 0; q < 4; q++) {
            unsigned int u = s_keys[tid * 4 + q];
            if ((u & himask) == pfx) atomicAdd(&hist[(u >> shift) & 255], 1u);
        }
        __syncthreads();
        if (wrp == 0)
            warp_select_bin(hist, kk, lane, shift, pfx, &sel_prefix, &sel_kr);
        __syncthreads();
    }
    const unsigned int thr = sel_prefix;
    const float tval = __uint_as_float((thr & 0x80000000u) ? (thr & 0x7fffffffu) : ~thr);
    const float mband = 4.0e-3f * sqrtf(Q2 * 6.0e-5f) + 1.0e-4f;

    // ---- flag pass ----
#pragma unroll
    for (int q = 0; q < 4; q++) {
        int n = tid * 4 + q;
        float hb = s_h[n] * s_bst[n];
        unsigned char fl = (s_keys[n] >= thr) ? 1 : 0;
        if (fabsf(hb - tval) <= mband) {
            fl = 2;
            int pos = atomicAdd(&s_ccnt, 1);
            if (pos < CANDCAP) s_cnd_n[pos] = n;
        }
        s_flag[n] = fl;
    }
    __syncthreads();
    int ccnt = min(s_ccnt, CANDCAP);

    // ---- exact fp32 recompute for candidates from ORIGINAL weights+mask ----
    for (int c = wrp; c < ccnt; c += 8) {
        int n = s_cnd_n[c];
        const float* wrow = fw    + (size_t)n * CL;
        const float* mrow = fmask + (size_t)n * CL;
        float part = 0.f;
        for (int ee = lane; ee < cnt; ee += 32) {
            float2 pr = s_pair[ee];
            int j = __float_as_int(pr.y) >> 8;
            float wv = __ldg(&wrow[j]);
            float mv = __ldg(&mrow[j]);
            if (mv < 0.5f) part = fmaf(pr.x, wv, part);
        }
#pragma unroll
        for (int d = 16; d > 0; d >>= 1)
            part += __shfl_down_sync(0xFFFFFFFFu, part, d);
        if (lane == 0) {
            float h = part + fc1_b[n];
            s_h[n] = h;
            s_cnd_k[c] = f2u(h * s_bst[n]);
        }
    }
    __syncthreads();

    // ---- count definite-ins, resolve candidates exactly ----
    {
        int myc = 0;
#pragma unroll
        for (int q = 0; q < 4; q++) myc += (s_flag[tid * 4 + q] == 1);
#pragma unroll
        for (int d = 16; d > 0; d >>= 1) myc += __shfl_down_sync(0xFFFFFFFFu, myc, d);
        if (lane == 0) s_ic[wrp] = myc;
    }
    __syncthreads();
    if (tid == 0) {
        int ic = 0;
#pragma unroll
        for (int w = 0; w < 8; w++) ic += s_ic[w];
        int r = KFC - ic;
        if (r < 1) r = 1;
        if (r > ccnt) r = ccnt;
        for (int c = 0; c < ccnt; c++) s_used[c] = 0;
        unsigned int kth = 0u;
        for (int s = 0; s < r; s++) {
            int bi = -1; unsigned int bk = 0u;
            for (int c = 0; c < ccnt; c++)
                if (!s_used[c] && (bi < 0 || s_cnd_k[c] > bk)) { bi = c; bk = s_cnd_k[c]; }
            s_used[bi] = 1; kth = bk;
        }
        for (int c = 0; c < ccnt; c++)
            s_flag[s_cnd_n[c]] = (s_cnd_k[c] >= kth) ? 1 : 0;
    }
    __syncthreads();

    // ---- fc2 over winners ----
    float part[10];
#pragma unroll
    for (int c = 0; c < 10; c++) part[c] = 0.f;
#pragma unroll
    for (int q = 0; q < 4; q++) {
        int n = tid * 4 + q;
        unsigned char fl = s_flag[n];
        bool win = (fl == 1) || (fl == 2 && s_keys[n] >= thr);
        if (win) {
            float hv = s_h[n];
#pragma unroll
            for (int c = 0; c < 10; c++)
                part[c] = fmaf(hv, w2[c * NFC + n], part[c]);
        }
    }
#pragma unroll
    for (int c = 0; c < 10; c++) {
        float pv = part[c];
#pragma unroll
        for (int d = 16; d > 0; d >>= 1)
            pv += __shfl_down_sync(0xFFFFFFFFu, pv, d);
        if (lane == 0) s_red[wrp][c] = pv;
    }
    __syncthreads();
    if (tid < 10) {
        float s = 0.f;
#pragma unroll
        for (int w = 0; w < 8; w++) s += s_red[w][tid];
        s_logits[tid] = s + b2[tid];
    }
    __syncthreads();
    if (tid == 0) {
        float mx = s_logits[0];
        for (int c = 1; c < 10; c++) mx = fmaxf(mx, s_logits[c]);
        float se = 0.f;
        for (int c = 0; c < 10; c++) se += expf(s_logits[c] - mx);
        s_lse = mx + logf(se);
    }
    __syncthreads();
    if (tid < 10) out[b * 10 + tid] = s_logits[tid] - s_lse;
}

// ================= launch =================
extern "C" void kernel_launch(void* const* d_in, const int* in_sizes, int n_in,
                              void* d_out, int out_size)
{
    const float* x        = (const float*)d_in[0];
    const float* c1_w     = (const float*)d_in[1];
    const float* c1_b     = (const float*)d_in[2];
    const float* duty_cnn = (const float*)d_in[3];
    const float* fc1_w    = (const float*)d_in[4];
    const float* fc1_mask = (const float*)d_in[5];
    const float* fc1_b    = (const float*)d_in[6];
    const float* duty_fc  = (const float*)d_in[7];
    const float* fc2_w    = (const float*)d_in[8];
    const float* fc2_b    = (const float*)d_in[9];
    float* out = (float*)d_out;

    cudaFuncSetAttribute(k_conv_pool_kw,
                         cudaFuncAttributeMaxDynamicSharedMemorySize, K1_DSM);

    k_prep<<<dim3(CL / 32, NFC / 32), dim3(32, 8)>>>(fc1_w, fc1_mask);
    k_conv_pool_kw<<<BATCH, T1, K1_DSM>>>(x, c1_w, c1_b, duty_cnn);
    k_fc_out<<<BATCH, T2>>>(fc1_w, fc1_mask, fc1_b, duty_fc, fc2_w, fc2_b, out);
}

// round 15
// speedup vs baseline: 1.2292x; 1.2292x over previous
#include <cuda_runtime.h>
#include <cuda_fp16.h>
#include <math.h>

// ---------------- problem constants ----------------
#define BATCH   4096
#define C1      64
#define IMH     28
#define IMW     28
#define PH      12
#define POS     (PH*PH)         // 144
#define CL      (C1*POS)        // 9216
#define NFC     1024
#define K1K     400
#define KFC     100
#define CAP     512
#define CANDCAP 128
#define CAND1   512

// K1 dynamic smem: keys 36864 + img 3136 + dup'd half2 weights 6400
#define OFF_KEYS 0
#define OFF_IMG  36864
#define OFF_W2H  40000
#define K1_DSM   46400

// ---------------- scratch (static device globals) ----------------
__device__ __align__(16) __half g_Wh[CL * NFC];       // masked fc1_w^T fp16, 18.9 MB
__device__ __align__(16) float2 g_pair[BATCH * CAP];  // {val, as_float(j*256)}
__device__ int            g_cnt[BATCH];

// order-preserving float <-> uint transforms
__device__ __forceinline__ unsigned int f2u(float f) {
    unsigned int u = __float_as_uint(f);
    return (u & 0x80000000u) ? ~u : (u | 0x80000000u);
}
__device__ __forceinline__ float u2f(unsigned int u) {
    unsigned int b = (u & 0x80000000u) ? (u & 0x7fffffffu) : ~u;
    return __uint_as_float(b);
}

// warp-parallel exact bin selection over hist[256]
__device__ __forceinline__ void warp_select_bin(
    const unsigned int* hist, int kk, int lane, int shift, unsigned int pfx,
    volatile unsigned int* sel_prefix, volatile int* sel_kr)
{
    int base = 255 - lane * 8;
    unsigned int hb[8];
    unsigned int s = 0;
#pragma unroll
    for (int q = 0; q < 8; q++) { hb[q] = hist[base - q]; s += hb[q]; }
    unsigned int incl = s;
#pragma unroll
    for (int d = 1; d < 32; d <<= 1) {
        unsigned int t = __shfl_up_sync(0xFFFFFFFFu, incl, d);
        if (lane >= d) incl += t;
    }
    unsigned int excl = incl - s;
    if (excl < (unsigned)kk && (unsigned)kk <= incl) {
        unsigned int acc = excl;
#pragma unroll
        for (int q = 0; q < 8; q++) {
            if (acc + hb[q] >= (unsigned)kk) {
                *sel_prefix = pfx | ((unsigned)(base - q) << shift);
                *sel_kr = kk - (int)acc;
                break;
            }
            acc += hb[q];
        }
    }
}

// exact fp32 pooled conv value (incl. bias) for flat index i
__device__ __forceinline__ float exact_pooled(const float* img, const float* wts,
                                              const float* bias, int i) {
    int c = i / POS, pos = i - c * POS;
    int py = pos / PH, px = pos - py * PH;
    const float* wc = wts + c * 25;
    float m = -1e30f;
#pragma unroll
    for (int q = 0; q < 4; q++) {
        int r0 = py * 2 + (q >> 1), c0 = px * 2 + (q & 1);
        float s = 0.f;
#pragma unroll
        for (int u = 0; u < 5; u++)
#pragma unroll
            for (int v = 0; v < 5; v++)
                s = fmaf(img[(r0 + u) * IMW + c0 + v], wc[u * 5 + v], s);
        m = fmaxf(m, s);
    }
    return m + bias[c];
}

// ================= K0: mask + transpose + fp16-convert fc1 weights ============
__global__ void k_prep(const float* __restrict__ w, const float* __restrict__ m) {
    __shared__ float tile[32][33];
    int jb = blockIdx.x * 32;
    int nb = blockIdx.y * 32;
    int tx = threadIdx.x, ty = threadIdx.y;   // (32, 8)
#pragma unroll
    for (int r = 0; r < 32; r += 8) {
        int n = nb + ty + r;
        int j = jb + tx;
        float wv = w[n * CL + j];
        float mv = m[n * CL + j];
        tile[ty + r][tx] = (mv < 0.5f) ? wv : 0.0f;
    }
    __syncthreads();
#pragma unroll
    for (int r = 0; r < 32; r += 8) {
        int j = jb + ty + r;
        int n = nb + tx;
        g_Wh[j * NFC + n] = __float2half(tile[tx][ty + r]);
    }
}

// ================= K1: HFMA2 conv + pool + repaired kwinners(400/9216) ========
#define T1 288

__global__ void __launch_bounds__(T1) k_conv_pool_kw(
    const float* __restrict__ x, const float* __restrict__ cw,
    const float* __restrict__ cb, const float* __restrict__ duty)
{
    extern __shared__ unsigned char dysm[];
    unsigned int* s_keys = (unsigned int*)(dysm + OFF_KEYS);
    float*        img    = (float*)(dysm + OFF_IMG);
    __half2*      w2h    = (__half2*)(dysm + OFF_W2H);   // dup'd {w,w}

    __shared__ float wts[C1 * 25];
    __shared__ float bias[C1];
    __shared__ float boost[C1];
    __shared__ float s_Ac[C1];
    __shared__ unsigned int hist[256];
    __shared__ int s_wsum[9];
    __shared__ float s_pm[9];
    __shared__ unsigned int sel_prefix;
    __shared__ int sel_kr;
    __shared__ int sel_total;
    __shared__ int s_ic9[9];
    __shared__ int s_ccnt;
    __shared__ int s_cnd_i[CAND1];
    __shared__ unsigned int s_cnd_k[CAND1];
    __shared__ float s_P;

    const int tid  = threadIdx.x;
    const int b    = blockIdx.x;
    const int lane = tid & 31, wrp = tid >> 5;

    // ---- load img (track max|.|), weights (fp32 + dup'd half2) ----
    const float* xb = x + b * (IMH * IMW);
    float pm = 0.f;
    for (int i = tid; i < IMH * IMW; i += T1) {
        float v = xb[i];
        img[i] = v;
        pm = fmaxf(pm, fabsf(v));
    }
#pragma unroll
    for (int d = 16; d > 0; d >>= 1)
        pm = fmaxf(pm, __shfl_down_sync(0xFFFFFFFFu, pm, d));
    if (lane == 0) s_pm[wrp] = pm;
    for (int i = tid; i < C1 * 25; i += T1) {
        float wv = cw[i];
        wts[i] = wv;
        w2h[i] = __float2half2_rn(wv);
    }
    if (tid == 0) s_ccnt = 0;
    __syncthreads();
    if (tid < C1) {
        bias[tid]  = cb[tid];
        boost[tid] = expf(400.0f / 9216.0f - duty[tid]);
        float a = 0.f;
        for (int k = 0; k < 25; k++) a += fabsf(wts[tid * 25 + k]);
        s_Ac[tid] = a;
    }
    if (tid == 0) {
        float P = 0.f;
        for (int w = 0; w < 9; w++) P = fmaxf(P, s_pm[w]);
        s_P = P;
    }
    __syncthreads();
    const float P = s_P;

    // ---- conv 5x5 + maxpool 2x2 in packed half2 (HFMA2) ----
    {
        int pos = tid % POS;
        int cg  = tid / POS;
        int py = pos / PH, px = pos % PH;
        int r0 = py * 2, c0 = px * 2;
        __half2 pp[30];    // pp[u*5+v] = {p[u][v], p[u][v+1]}
#pragma unroll
        for (int u = 0; u < 6; u++) {
            float r[6];
#pragma unroll
            for (int v = 0; v < 6; v++) r[v] = img[(r0 + u) * IMW + (c0 + v)];
#pragma unroll
            for (int v = 0; v < 5; v++)
                pp[u * 5 + v] = __floats2half2_rn(r[v], r[v + 1]);
        }
        int cbase = cg * 32;
        for (int cc = 0; cc < 32; cc++) {
            int c = cbase + cc;
            const __half2* wc = w2h + c * 25;
            __half2 a01 = __float2half2_rn(0.f);
            __half2 a23 = __float2half2_rn(0.f);
#pragma unroll
            for (int u = 0; u < 5; u++) {
#pragma unroll
                for (int v = 0; v < 5; v++) {
                    __half2 w2 = wc[u * 5 + v];
                    a01 = __hfma2(pp[u * 5 + v], w2, a01);
                    a23 = __hfma2(pp[(u + 1) * 5 + v], w2, a23);
                }
            }
            float2 f01 = __half22float2(a01);
            float2 f23 = __half22float2(a23);
            float pv = fmaxf(fmaxf(f01.x, f01.y), fmaxf(f23.x, f23.y)) + bias[c];
            s_keys[c * POS + pos] = f2u(pv * boost[c]);
        }
    }
    __syncthreads();

    // ---- radix select approx rank-400 threshold ----
    if (tid == 0) { sel_prefix = 0u; sel_kr = K1K; }
    __syncthreads();
    for (int shift = 24; shift >= 0; shift -= 8) {
        if (tid < 256) hist[tid] = 0u;
        __syncthreads();
        unsigned int pfx    = sel_prefix;
        int          kk     = sel_kr;
        unsigned int himask = (shift == 24) ? 0u : (0xFFFFFFFFu << (shift + 8));
        for (int i = tid; i < CL; i += T1) {
            unsigned int u = s_keys[i];
            if ((u & himask) == pfx) atomicAdd(&hist[(u >> shift) & 255], 1u);
        }
        __syncthreads();
        if (wrp == 0)
            warp_select_bin(hist, kk, lane, shift, pfx, &sel_prefix, &sel_kr);
        __syncthreads();
    }
    const unsigned int thr = sel_prefix;
    const float tval = u2f(thr);

    // ---- flag pass: count definite-ins, collect boundary candidates ----
    const float bconst = 6.0e-3f * P;    // fp16-accum band scale
    int myic = 0;
    for (int i = tid; i < CL; i += T1) {
        unsigned int k = s_keys[i];
        int c = i / POS;
        float band = bconst * s_Ac[c] * boost[c];
        bool cand = fabsf(u2f(k) - tval) <= band;
        if (cand) {
            int pos = atomicAdd(&s_ccnt, 1);
            if (pos < CAND1) s_cnd_i[pos] = i;
        } else if (k >= thr) {
            myic++;
        }
    }
#pragma unroll
    for (int d = 16; d > 0; d >>= 1) myic += __shfl_down_sync(0xFFFFFFFFu, myic, d);
    if (lane == 0) s_ic9[wrp] = myic;
    __syncthreads();
    int ccnt = min(s_ccnt, CAND1);

    // ---- exact fp32 recompute for candidate keys ----
    for (int c = tid; c < ccnt; c += T1) {
        int i = s_cnd_i[c];
        float ex = exact_pooled(img, wts, bias, i);
        s_cnd_k[c] = f2u(ex * boost[i / POS]);
    }
    __syncthreads();

    // ---- resolve candidates exactly (count-based, >= kth tie semantics) ----
    int ic = 0;
#pragma unroll
    for (int w = 0; w < 9; w++) ic += s_ic9[w];
    int r = K1K - ic;
    if (r < 0) r = 0;
    if (s_ccnt <= CAND1) {
        for (int c = tid; c < ccnt; c += T1) {
            unsigned int kc = s_cnd_k[c];
            int cg = 0;
            for (int d = 0; d < ccnt; d++) cg += (s_cnd_k[d] > kc);
            s_keys[s_cnd_i[c]] = (cg < r) ? 0xFFFFFFFFu : 0u;
        }
    }
    __syncthreads();

    // ---- deterministic compaction with exact fp32 value recompute ----
    int mycnt = 0;
    for (int i = tid; i < CL; i += T1)
        if (s_keys[i] >= thr) mycnt++;

    int v = mycnt;
#pragma unroll
    for (int d = 1; d < 32; d <<= 1) {
        int t = __shfl_up_sync(0xFFFFFFFFu, v, d);
        if (lane >= d) v += t;
    }
    if (lane == 31) s_wsum[wrp] = v;
    __syncthreads();
    if (tid == 0) {
        int a = 0;
        for (int w = 0; w < 9; w++) { int t = s_wsum[w]; s_wsum[w] = a; a += t; }
        sel_total = a;
    }
    __syncthreads();
    int off = s_wsum[wrp] + v - mycnt;
    for (int i = tid; i < CL; i += T1) {
        if (s_keys[i] >= thr) {
            if (off < CAP) {
                float ev = exact_pooled(img, wts, bias, i);
                g_pair[b * CAP + off] =
                    make_float2(ev, __int_as_float(i << 8));   // j * (NFC/4)
            }
            off++;
        }
    }
    if (tid == 0) g_cnt[b] = sel_total > CAP ? CAP : sel_total;
}

// ================= K2: fp16 fc1 + exact-boundary kwinners + fc2 + lsm =========
#define T2 256

__global__ void __launch_bounds__(T2) k_fc_out(
    const float* __restrict__ fw,    const float* __restrict__ fmask,
    const float* __restrict__ fc1_b, const float* __restrict__ duty_fc,
    const float* __restrict__ w2,    const float* __restrict__ b2,
    float* __restrict__ out)
{
    __shared__ float2        s_pair[CAP];
    __shared__ float         s_h[NFC];
    __shared__ float         s_bst[NFC];
    __shared__ unsigned int  s_keys[NFC];
    __shared__ unsigned char s_flag[NFC];
    __shared__ unsigned int  hist[256];
    __shared__ unsigned int  sel_prefix;
    __shared__ int           sel_kr;
    __shared__ float         s_red[8][10];
    __shared__ float         s_logits[10];
    __shared__ float         s_lse;
    __shared__ float         s_Q[8];
    __shared__ int           s_ic[8];
    __shared__ int           s_ccnt;
    __shared__ int           s_cnd_n[CANDCAP];
    __shared__ unsigned int  s_cnd_k[CANDCAP];
    __shared__ unsigned char s_used[CANDCAP];

    const int tid  = threadIdx.x;
    const int b    = blockIdx.x;
    const int lane = tid & 31, wrp = tid >> 5;

    int cnt = g_cnt[b];
    float myQ = 0.f;
    for (int i = tid; i < cnt; i += T2) {
        float2 pr = g_pair[b * CAP + i];
        s_pair[i] = pr;
        myQ = fmaf(pr.x, pr.x, myQ);
    }
#pragma unroll
    for (int d = 16; d > 0; d >>= 1) myQ += __shfl_down_sync(0xFFFFFFFFu, myQ, d);
    if (lane == 0) s_Q[wrp] = myQ;
    if (tid == 0) s_ccnt = 0;
    __syncthreads();
    float Q2 = 0.f;
#pragma unroll
    for (int w = 0; w < 8; w++) Q2 += s_Q[w];

    // ---- fp16 sparse accumulate ----
    float a0 = 0.f, a1 = 0.f, a2 = 0.f, a3 = 0.f;
    const uint2* __restrict__ W8 = (const uint2*)g_Wh;
#pragma unroll 8
    for (int e = 0; e < cnt; e++) {
        float2 pv = s_pair[e];
        int jn = __float_as_int(pv.y);
        uint2 wraw = __ldg(&W8[jn + tid]);
        float2 f01 = __half22float2(*(const __half2*)&wraw.x);
        float2 f23 = __half22float2(*(const __half2*)&wraw.y);
        a0 = fmaf(pv.x, f01.x, a0);
        a1 = fmaf(pv.x, f01.y, a1);
        a2 = fmaf(pv.x, f23.x, a2);
        a3 = fmaf(pv.x, f23.y, a3);
    }

    const float kdn = 100.0f / 1024.0f;
    {
        int n = tid * 4;
        float h0 = a0 + fc1_b[n],     h1 = a1 + fc1_b[n + 1];
        float h2 = a2 + fc1_b[n + 2], h3 = a3 + fc1_b[n + 3];
        float b0 = expf(kdn - duty_fc[n]),      b1 = expf(kdn - duty_fc[n + 1]);
        float b2v = expf(kdn - duty_fc[n + 2]), b3 = expf(kdn - duty_fc[n + 3]);
        s_h[n] = h0; s_h[n+1] = h1; s_h[n+2] = h2; s_h[n+3] = h3;
        s_bst[n] = b0; s_bst[n+1] = b1; s_bst[n+2] = b2v; s_bst[n+3] = b3;
        s_keys[n]   = f2u(h0 * b0);
        s_keys[n+1] = f2u(h1 * b1);
        s_keys[n+2] = f2u(h2 * b2v);
        s_keys[n+3] = f2u(h3 * b3);
    }
    __syncthreads();

    // ---- radix select approx rank-100 threshold ----
    if (tid == 0) { sel_prefix = 0u; sel_kr = KFC; }
    __syncthreads();
    for (int shift = 24; shift >= 0; shift -= 8) {
        hist[tid] = 0u;
        __syncthreads();
        unsigned int pfx    = sel_prefix;
        int          kk     = sel_kr;
        unsigned int himask = (shift == 24) ? 0u : (0xFFFFFFFFu << (shift + 8));
#pragma unroll
        for (int q = 0; q < 4; q++) {
            unsigned int u = s_keys[tid * 4 + q];
            if ((u & himask) == pfx) atomicAdd(&hist[(u >> shift) & 255], 1u);
        }
        __syncthreads();
        if (wrp == 0)
            warp_select_bin(hist, kk, lane, shift, pfx, &sel_prefix, &sel_kr);
        __syncthreads();
    }
    const unsigned int thr = sel_prefix;
    const float tval = __uint_as_float((thr & 0x80000000u) ? (thr & 0x7fffffffu) : ~thr);
    const float mband = 4.0e-3f * sqrtf(Q2 * 6.0e-5f) + 1.0e-4f;

    // ---- flag pass ----
#pragma unroll
    for (int q = 0; q < 4; q++) {
        int n = tid * 4 + q;
        float hb = s_h[n] * s_bst[n];
        unsigned char fl = (s_keys[n] >= thr) ? 1 : 0;
        if (fabsf(hb - tval) <= mband) {
            fl = 2;
            int pos = atomicAdd(&s_ccnt, 1);
            if (pos < CANDCAP) s_cnd_n[pos] = n;
        }
        s_flag[n] = fl;
    }
    __syncthreads();
    int ccnt = min(s_ccnt, CANDCAP);

    // ---- exact fp32 recompute for candidates from ORIGINAL weights+mask ----
    for (int c = wrp; c < ccnt; c += 8) {
        int n = s_cnd_n[c];
        const float* wrow = fw    + (size_t)n * CL;
        const float* mrow = fmask + (size_t)n * CL;
        float part = 0.f;
        for (int ee = lane; ee < cnt; ee += 32) {
            float2 pr = s_pair[ee];
            int j = __float_as_int(pr.y) >> 8;
            float wv = __ldg(&wrow[j]);
            float mv = __ldg(&mrow[j]);
            if (mv < 0.5f) part = fmaf(pr.x, wv, part);
        }
#pragma unroll
        for (int d = 16; d > 0; d >>= 1)
            part += __shfl_down_sync(0xFFFFFFFFu, part, d);
        if (lane == 0) {
            float h = part + fc1_b[n];
            s_h[n] = h;
            s_cnd_k[c] = f2u(h * s_bst[n]);
        }
    }
    __syncthreads();

    // ---- count definite-ins, resolve candidates exactly ----
    {
        int myc = 0;
#pragma unroll
        for (int q = 0; q < 4; q++) myc += (s_flag[tid * 4 + q] == 1);
#pragma unroll
        for (int d = 16; d > 0; d >>= 1) myc += __shfl_down_sync(0xFFFFFFFFu, myc, d);
        if (lane == 0) s_ic[wrp] = myc;
    }
    __syncthreads();
    if (tid == 0) {
        int ic = 0;
#pragma unroll
        for (int w = 0; w < 8; w++) ic += s_ic[w];
        int r = KFC - ic;
        if (r < 1) r = 1;
        if (r > ccnt) r = ccnt;
        for (int c = 0; c < ccnt; c++) s_used[c] = 0;
        unsigned int kth = 0u;
        for (int s = 0; s < r; s++) {
            int bi = -1; unsigned int bk = 0u;
            for (int c = 0; c < ccnt; c++)
                if (!s_used[c] && (bi < 0 || s_cnd_k[c] > bk)) { bi = c; bk = s_cnd_k[c]; }
            s_used[bi] = 1; kth = bk;
        }
        for (int c = 0; c < ccnt; c++)
            s_flag[s_cnd_n[c]] = (s_cnd_k[c] >= kth) ? 1 : 0;
    }
    __syncthreads();

    // ---- fc2 over winners ----
    float part[10];
#pragma unroll
    for (int c = 0; c < 10; c++) part[c] = 0.f;
#pragma unroll
    for (int q = 0; q < 4; q++) {
        int n = tid * 4 + q;
        unsigned char fl = s_flag[n];
        bool win = (fl == 1) || (fl == 2 && s_keys[n] >= thr);
        if (win) {
            float hv = s_h[n];
#pragma unroll
            for (int c = 0; c < 10; c++)
                part[c] = fmaf(hv, w2[c * NFC + n], part[c]);
        }
    }
#pragma unroll
    for (int c = 0; c < 10; c++) {
        float pv = part[c];
#pragma unroll
        for (int d = 16; d > 0; d >>= 1)
            pv += __shfl_down_sync(0xFFFFFFFFu, pv, d);
        if (lane == 0) s_red[wrp][c] = pv;
    }
    __syncthreads();
    if (tid < 10) {
        float s = 0.f;
#pragma unroll
        for (int w = 0; w < 8; w++) s += s_red[w][tid];
        s_logits[tid] = s + b2[tid];
    }
    __syncthreads();
    if (tid == 0) {
        float mx = s_logits[0];
        for (int c = 1; c < 10; c++) mx = fmaxf(mx, s_logits[c]);
        float se = 0.f;
        for (int c = 0; c < 10; c++) se += expf(s_logits[c] - mx);
        s_lse = mx + logf(se);
    }
    __syncthreads();
    if (tid < 10) out[b * 10 + tid] = s_logits[tid] - s_lse;
}

// ================= launch =================
extern "C" void kernel_launch(void* const* d_in, const int* in_sizes, int n_in,
                              void* d_out, int out_size)
{
    const float* x        = (const float*)d_in[0];
    const float* c1_w     = (const float*)d_in[1];
    const float* c1_b     = (const float*)d_in[2];
    const float* duty_cnn = (const float*)d_in[3];
    const float* fc1_w    = (const float*)d_in[4];
    const float* fc1_mask = (const float*)d_in[5];
    const float* fc1_b    = (const float*)d_in[6];
    const float* duty_fc  = (const float*)d_in[7];
    const float* fc2_w    = (const float*)d_in[8];
    const float* fc2_b    = (const float*)d_in[9];
    float* out = (float*)d_out;

    cudaFuncSetAttribute(k_conv_pool_kw,
                         cudaFuncAttributeMaxDynamicSharedMemorySize, K1_DSM);

    k_prep<<<dim3(CL / 32, NFC / 32), dim3(32, 8)>>>(fc1_w, fc1_mask);
    k_conv_pool_kw<<<BATCH, T1, K1_DSM>>>(x, c1_w, c1_b, duty_cnn);
    k_fc_out<<<BATCH, T2>>>(fc1_w, fc1_mask, fc1_b, duty_fc, fc2_w, fc2_b, out);
}

// round 16
// speedup vs baseline: 1.2930x; 1.0519x over previous
#include <cuda_runtime.h>
#include <cuda_fp16.h>
#include <math.h>

// ---------------- problem constants ----------------
#define BATCH   4096
#define C1      64
#define IMH     28
#define IMW     28
#define PH      12
#define POS     (PH*PH)         // 144
#define CL      (C1*POS)        // 9216
#define NFC     1024
#define K1K     400
#define KFC     100
#define CAP     512
#define CANDCAP 128

#define NPREP   9216            // prep tiles (288 x 32 grid)
#define NGRID   (BATCH + NPREP) // 13312 = 1024 groups of (4 conv + 9 prep)

// ---------------- scratch (static device globals) ----------------
__device__ __align__(16) __half g_Wh[CL * NFC];       // masked fc1_w^T fp16, 18.9 MB
__device__ __align__(16) float2 g_pair[BATCH * CAP];  // {val, as_float(i*128)}
__device__ int            g_cnt[BATCH];

// order-preserving float <-> uint transforms
__device__ __forceinline__ unsigned int f2u(float f) {
    unsigned int u = __float_as_uint(f);
    return (u & 0x80000000u) ? ~u : (u | 0x80000000u);
}
__device__ __forceinline__ float u2f(unsigned int u) {
    unsigned int b = (u & 0x80000000u) ? (u & 0x7fffffffu) : ~u;
    return __uint_as_float(b);
}

// warp-parallel exact bin selection over hist[256]
__device__ __forceinline__ void warp_select_bin(
    const unsigned int* hist, int kk, int lane, int shift, unsigned int pfx,
    volatile unsigned int* sel_prefix, volatile int* sel_kr)
{
    int base = 255 - lane * 8;
    unsigned int hb[8];
    unsigned int s = 0;
#pragma unroll
    for (int q = 0; q < 8; q++) { hb[q] = hist[base - q]; s += hb[q]; }
    unsigned int incl = s;
#pragma unroll
    for (int d = 1; d < 32; d <<= 1) {
        unsigned int t = __shfl_up_sync(0xFFFFFFFFu, incl, d);
        if (lane >= d) incl += t;
    }
    unsigned int excl = incl - s;
    if (excl < (unsigned)kk && (unsigned)kk <= incl) {
        unsigned int acc = excl;
#pragma unroll
        for (int q = 0; q < 8; q++) {
            if (acc + hb[q] >= (unsigned)kk) {
                *sel_prefix = pfx | ((unsigned)(base - q) << shift);
                *sel_kr = kk - (int)acc;
                break;
            }
            acc += hb[q];
        }
    }
}

// ================= K1 (merged): conv CTAs + weight-prep CTAs ==================
#define T1 288

__global__ void __launch_bounds__(T1) k_conv_prep(
    const float* __restrict__ x, const float* __restrict__ cw,
    const float* __restrict__ cb, const float* __restrict__ duty,
    const float* __restrict__ fw, const float* __restrict__ fm)
{
    __shared__ unsigned int s_keys[CL];    // 36 KB
    __shared__ float img[IMH * IMW];
    __shared__ float wts[C1 * 25];         // aliased as prep tile (needs 4224 B)
    __shared__ float bias[C1];
    __shared__ float boost[C1];
    __shared__ unsigned int hist[256];
    __shared__ int s_wsum[16];
    __shared__ unsigned int sel_prefix;
    __shared__ int sel_kr;
    __shared__ int sel_total;

    const int tid = threadIdx.x;
    const int grp = blockIdx.x / 13;
    const int rnk = blockIdx.x % 13;
    const int lane = tid & 31, wrp = tid >> 5;

    // ---------------- prep branch: mask+transpose+fp16 one 32x32 tile --------
    if (rnk >= 4) {
        int p  = grp * 9 + (rnk - 4);          // 0..9215
        int jb = (p % 288) * 32;
        int nb = (p / 288) * 32;
        float (*tile)[33] = (float (*)[33])wts;
        int tx = tid & 31, ty = tid >> 5;      // threads 0..255 -> (32,8)
        if (tid < 256) {
#pragma unroll
            for (int r = 0; r < 32; r += 8) {
                int n = nb + ty + r;
                int j = jb + tx;
                float wv = fw[(size_t)n * CL + j];
                float mv = fm[(size_t)n * CL + j];
                tile[ty + r][tx] = (mv < 0.5f) ? wv : 0.0f;
            }
        }
        __syncthreads();
        if (tid < 256) {
#pragma unroll
            for (int r = 0; r < 32; r += 8) {
                int j = jb + ty + r;
                int n = nb + tx;
                g_Wh[(size_t)j * NFC + n] = __float2half(tile[tx][ty + r]);
            }
        }
        return;
    }

    // ---------------- conv branch ----------------
    const int b = grp * 4 + rnk;               // 0..4095

    const float* xb = x + b * (IMH * IMW);
    for (int i = tid; i < IMH * IMW; i += T1) img[i] = xb[i];
    for (int i = tid; i < C1 * 25;   i += T1) wts[i] = cw[i];
    if (tid < C1) {
        bias[tid]  = cb[tid];
        boost[tid] = expf(400.0f / 9216.0f - duty[tid]);
    }
    __syncthreads();

    // ---- conv 5x5 + maxpool 2x2, scalar fp32, patch in registers ----
    {
        int pos = tid % POS;
        int cg  = tid / POS;
        int py = pos / PH, px = pos % PH;
        int r0 = py * 2, c0 = px * 2;
        float p[36];
#pragma unroll
        for (int u = 0; u < 6; u++)
#pragma unroll
            for (int v = 0; v < 6; v++)
                p[u * 6 + v] = img[(r0 + u) * IMW + (c0 + v)];
        int cbase = cg * 32;
        for (int cc = 0; cc < 32; cc++) {
            int c = cbase + cc;
            const float* wc = wts + c * 25;
            float s00 = 0.f, s01 = 0.f, s10 = 0.f, s11 = 0.f;
#pragma unroll
            for (int u = 0; u < 5; u++) {
#pragma unroll
                for (int v = 0; v < 5; v++) {
                    float wv = wc[u * 5 + v];
                    s00 = fmaf(p[u * 6 + v],     wv, s00);
                    s01 = fmaf(p[u * 6 + v + 1], wv, s01);
                    s10 = fmaf(p[u * 6 + 6 + v], wv, s10);
                    s11 = fmaf(p[u * 6 + 7 + v], wv, s11);
                }
            }
            float pv = fmaxf(fmaxf(s00, s01), fmaxf(s10, s11)) + bias[c];
            s_keys[c * POS + pos] = f2u(pv * boost[c]);
        }
    }
    __syncthreads();

    // ---- exact k-th largest via 4-pass radix select (warp-parallel bins) ----
    if (tid == 0) { sel_prefix = 0u; sel_kr = K1K; }
    __syncthreads();
    for (int shift = 24; shift >= 0; shift -= 8) {
        if (tid < 256) hist[tid] = 0u;
        __syncthreads();
        unsigned int pfx    = sel_prefix;
        int          kk     = sel_kr;
        unsigned int himask = (shift == 24) ? 0u : (0xFFFFFFFFu << (shift + 8));
        for (int i = tid; i < CL; i += T1) {
            unsigned int u = s_keys[i];
            if ((u & himask) == pfx) atomicAdd(&hist[(u >> shift) & 255], 1u);
        }
        __syncthreads();
        if (wrp == 0)
            warp_select_bin(hist, kk, lane, shift, pfx, &sel_prefix, &sel_kr);
        __syncthreads();
    }
    unsigned int thr = sel_prefix;

    // ---- deterministic compaction (fused pair write, stride i<<7) ----
    int mycnt = 0;
    for (int i = tid; i < CL; i += T1)
        if (s_keys[i] >= thr) mycnt++;

    int v = mycnt;
#pragma unroll
    for (int d = 1; d < 32; d <<= 1) {
        int t = __shfl_up_sync(0xFFFFFFFFu, v, d);
        if (lane >= d) v += t;
    }
    if (lane == 31) s_wsum[wrp] = v;
    __syncthreads();
    if (tid == 0) {
        int a = 0;
        for (int w = 0; w < T1 / 32; w++) { int t = s_wsum[w]; s_wsum[w] = a; a += t; }
        sel_total = a;
    }
    __syncthreads();
    int off = s_wsum[wrp] + v - mycnt;
    for (int i = tid; i < CL; i += T1) {
        unsigned int k = s_keys[i];
        if (k >= thr) {
            if (off < CAP) {
                g_pair[b * CAP + off] =
                    make_float2(u2f(k) / boost[i / POS],
                                __int_as_float(i << 7));   // i * (NFC/8)
            }
            off++;
        }
    }
    if (tid == 0) g_cnt[b] = sel_total > CAP ? CAP : sel_total;
}

// ================= K2: fp16 fc1 (uint4, 8 neurons/thread) + exact kwinners ====
#define T2 128

__global__ void __launch_bounds__(T2) k_fc_out(
    const float* __restrict__ fw,    const float* __restrict__ fmask,
    const float* __restrict__ fc1_b, const float* __restrict__ duty_fc,
    const float* __restrict__ w2,    const float* __restrict__ b2,
    float* __restrict__ out)
{
    __shared__ float2        s_pair[CAP];
    __shared__ float         s_h[NFC];
    __shared__ float         s_bst[NFC];
    __shared__ unsigned int  s_keys[NFC];
    __shared__ unsigned char s_flag[NFC];
    __shared__ unsigned int  hist[256];
    __shared__ unsigned int  sel_prefix;
    __shared__ int           sel_kr;
    __shared__ float         s_red[4][10];
    __shared__ float         s_logits[10];
    __shared__ float         s_lse;
    __shared__ float         s_Q[4];
    __shared__ int           s_ic[4];
    __shared__ int           s_ccnt;
    __shared__ int           s_cnd_n[CANDCAP];
    __shared__ unsigned int  s_cnd_k[CANDCAP];
    __shared__ unsigned char s_used[CANDCAP];

    const int tid  = threadIdx.x;
    const int b    = blockIdx.x;
    const int lane = tid & 31, wrp = tid >> 5;

    int cnt = g_cnt[b];
    float myQ = 0.f;
    for (int i = tid; i < cnt; i += T2) {
        float2 pr = g_pair[b * CAP + i];
        s_pair[i] = pr;
        myQ = fmaf(pr.x, pr.x, myQ);
    }
#pragma unroll
    for (int d = 16; d > 0; d >>= 1) myQ += __shfl_down_sync(0xFFFFFFFFu, myQ, d);
    if (lane == 0) s_Q[wrp] = myQ;
    if (tid == 0) s_ccnt = 0;
    __syncthreads();
    float Q2 = s_Q[0] + s_Q[1] + s_Q[2] + s_Q[3];

    // ---- fp16 sparse accumulate: LDG.128, 8 neurons per thread ----
    float a0 = 0.f, a1 = 0.f, a2 = 0.f, a3 = 0.f;
    float a4 = 0.f, a5 = 0.f, a6 = 0.f, a7 = 0.f;
    const uint4* __restrict__ W16 = (const uint4*)g_Wh;  // 16B = 8 halfs
#pragma unroll 8
    for (int e = 0; e < cnt; e++) {
        float2 pv = s_pair[e];
        int jn = __float_as_int(pv.y);           // i * 128
        uint4 wraw = __ldg(&W16[jn + tid]);
        float2 f01 = __half22float2(*(const __half2*)&wraw.x);
        float2 f23 = __half22float2(*(const __half2*)&wraw.y);
        float2 f45 = __half22float2(*(const __half2*)&wraw.z);
        float2 f67 = __half22float2(*(const __half2*)&wraw.w);
        a0 = fmaf(pv.x, f01.x, a0);
        a1 = fmaf(pv.x, f01.y, a1);
        a2 = fmaf(pv.x, f23.x, a2);
        a3 = fmaf(pv.x, f23.y, a3);
        a4 = fmaf(pv.x, f45.x, a4);
        a5 = fmaf(pv.x, f45.y, a5);
        a6 = fmaf(pv.x, f67.x, a6);
        a7 = fmaf(pv.x, f67.y, a7);
    }

    const float kdn = 100.0f / 1024.0f;
    {
        float av[8] = {a0, a1, a2, a3, a4, a5, a6, a7};
        int n = tid * 8;
#pragma unroll
        for (int q = 0; q < 8; q++) {
            float h = av[q] + fc1_b[n + q];
            float bo = expf(kdn - duty_fc[n + q]);
            s_h[n + q]    = h;
            s_bst[n + q]  = bo;
            s_keys[n + q] = f2u(h * bo);
        }
    }
    __syncthreads();

    // ---- radix select approx rank-100 threshold ----
    if (tid == 0) { sel_prefix = 0u; sel_kr = KFC; }
    __syncthreads();
    for (int shift = 24; shift >= 0; shift -= 8) {
        hist[tid] = 0u;
        hist[tid + 128] = 0u;
        __syncthreads();
        unsigned int pfx    = sel_prefix;
        int          kk     = sel_kr;
        unsigned int himask = (shift == 24) ? 0u : (0xFFFFFFFFu << (shift + 8));
#pragma unroll
        for (int q = 0; q < 8; q++) {
            unsigned int u = s_keys[tid * 8 + q];
            if ((u & himask) == pfx) atomicAdd(&hist[(u >> shift) & 255], 1u);
        }
        __syncthreads();
        if (wrp == 0)
            warp_select_bin(hist, kk, lane, shift, pfx, &sel_prefix, &sel_kr);
        __syncthreads();
    }
    const unsigned int thr = sel_prefix;
    const float tval = __uint_as_float((thr & 0x80000000u) ? (thr & 0x7fffffffu) : ~thr);
    const float mband = 4.0e-3f * sqrtf(Q2 * 6.0e-5f) + 1.0e-4f;

    // ---- flag pass ----
#pragma unroll
    for (int q = 0; q < 8; q++) {
        int n = tid * 8 + q;
        float hb = s_h[n] * s_bst[n];
        unsigned char fl = (s_keys[n] >= thr) ? 1 : 0;
        if (fabsf(hb - tval) <= mband) {
            fl = 2;
            int pos = atomicAdd(&s_ccnt, 1);
            if (pos < CANDCAP) s_cnd_n[pos] = n;
        }
        s_flag[n] = fl;
    }
    __syncthreads();
    int ccnt = min(s_ccnt, CANDCAP);

    // ---- exact fp32 recompute for candidates from ORIGINAL weights+mask ----
    for (int c = wrp; c < ccnt; c += 4) {
        int n = s_cnd_n[c];
        const float* wrow = fw    + (size_t)n * CL;
        const float* mrow = fmask + (size_t)n * CL;
        float part = 0.f;
        for (int ee = lane; ee < cnt; ee += 32) {
            float2 pr = s_pair[ee];
            int j = __float_as_int(pr.y) >> 7;
            float wv = __ldg(&wrow[j]);
            float mv = __ldg(&mrow[j]);
            if (mv < 0.5f) part = fmaf(pr.x, wv, part);
        }
#pragma unroll
        for (int d = 16; d > 0; d >>= 1)
            part += __shfl_down_sync(0xFFFFFFFFu, part, d);
        if (lane == 0) {
            float h = part + fc1_b[n];
            s_h[n] = h;
            s_cnd_k[c] = f2u(h * s_bst[n]);
        }
    }
    __syncthreads();

    // ---- count definite-ins, resolve candidates exactly ----
    {
        int myc = 0;
#pragma unroll
        for (int q = 0; q < 8; q++) myc += (s_flag[tid * 8 + q] == 1);
#pragma unroll
        for (int d = 16; d > 0; d >>= 1) myc += __shfl_down_sync(0xFFFFFFFFu, myc, d);
        if (lane == 0) s_ic[wrp] = myc;
    }
    __syncthreads();
    if (tid == 0) {
        int ic = s_ic[0] + s_ic[1] + s_ic[2] + s_ic[3];
        int r = KFC - ic;
        if (r < 1) r = 1;
        if (r > ccnt) r = ccnt;
        for (int c = 0; c < ccnt; c++) s_used[c] = 0;
        unsigned int kth = 0u;
        for (int s = 0; s < r; s++) {
            int bi = -1; unsigned int bk = 0u;
            for (int c = 0; c < ccnt; c++)
                if (!s_used[c] && (bi < 0 || s_cnd_k[c] > bk)) { bi = c; bk = s_cnd_k[c]; }
            s_used[bi] = 1; kth = bk;
        }
        for (int c = 0; c < ccnt; c++)
            s_flag[s_cnd_n[c]] = (s_cnd_k[c] >= kth) ? 1 : 0;
    }
    __syncthreads();

    // ---- fc2 over winners ----
    float part[10];
#pragma unroll
    for (int c = 0; c < 10; c++) part[c] = 0.f;
#pragma unroll
    for (int q = 0; q < 8; q++) {
        int n = tid * 8 + q;
        unsigned char fl = s_flag[n];
        bool win = (fl == 1) || (fl == 2 && s_keys[n] >= thr);
        if (win) {
            float hv = s_h[n];
#pragma unroll
            for (int c = 0; c < 10; c++)
                part[c] = fmaf(hv, w2[c * NFC + n], part[c]);
        }
    }
#pragma unroll
    for (int c = 0; c < 10; c++) {
        float pv = part[c];
#pragma unroll
        for (int d = 16; d > 0; d >>= 1)
            pv += __shfl_down_sync(0xFFFFFFFFu, pv, d);
        if (lane == 0) s_red[wrp][c] = pv;
    }
    __syncthreads();
    if (tid < 10) {
        float s = s_red[0][tid] + s_red[1][tid] + s_red[2][tid] + s_red[3][tid];
        s_logits[tid] = s + b2[tid];
    }
    __syncthreads();
    if (tid == 0) {
        float mx = s_logits[0];
        for (int c = 1; c < 10; c++) mx = fmaxf(mx, s_logits[c]);
        float se = 0.f;
        for (int c = 0; c < 10; c++) se += expf(s_logits[c] - mx);
        s_lse = mx + logf(se);
    }
    __syncthreads();
    if (tid < 10) out[b * 10 + tid] = s_logits[tid] - s_lse;
}

// ================= launch =================
extern "C" void kernel_launch(void* const* d_in, const int* in_sizes, int n_in,
                              void* d_out, int out_size)
{
    const float* x        = (const float*)d_in[0];
    const float* c1_w     = (const float*)d_in[1];
    const float* c1_b     = (const float*)d_in[2];
    const float* duty_cnn = (const float*)d_in[3];
    const float* fc1_w    = (const float*)d_in[4];
    const float* fc1_mask = (const float*)d_in[5];
    const float* fc1_b    = (const float*)d_in[6];
    const float* duty_fc  = (const float*)d_in[7];
    const float* fc2_w    = (const float*)d_in[8];
    const float* fc2_b    = (const float*)d_in[9];
    float* out = (float*)d_out;

    k_conv_prep<<<NGRID, T1>>>(x, c1_w, c1_b, duty_cnn, fc1_w, fc1_mask);
    k_fc_out<<<BATCH, T2>>>(fc1_w, fc1_mask, fc1_b, duty_fc, fc2_w, fc2_b, out);
}

// round 17
// speedup vs baseline: 1.3939x; 1.0780x over previous
#include <cuda_runtime.h>
#include <cuda_fp16.h>
#include <math.h>

// ---------------- problem constants ----------------
#define BATCH   4096
#define C1      64
#define IMH     28
#define IMW     28
#define PH      12
#define POS     (PH*PH)         // 144
#define CL      (C1*POS)        // 9216
#define NFC     1024
#define K1K     400
#define KFC     100
#define CAP     512
#define CANDCAP 128

// ---------------- scratch (static device globals) ----------------
__device__ __align__(16) __half g_Wh[CL * NFC];       // masked fc1_w^T fp16, 18.9 MB
__device__ __align__(16) float2 g_pair[BATCH * CAP];  // {val, as_float(i*128)}
__device__ int            g_cnt[BATCH];

// order-preserving float <-> uint transforms
__device__ __forceinline__ unsigned int f2u(float f) {
    unsigned int u = __float_as_uint(f);
    return (u & 0x80000000u) ? ~u : (u | 0x80000000u);
}
__device__ __forceinline__ float u2f(unsigned int u) {
    unsigned int b = (u & 0x80000000u) ? (u & 0x7fffffffu) : ~u;
    return __uint_as_float(b);
}

// warp-parallel exact bin selection over hist[256]
__device__ __forceinline__ void warp_select_bin(
    const unsigned int* hist, int kk, int lane, int shift, unsigned int pfx,
    volatile unsigned int* sel_prefix, volatile int* sel_kr)
{
    int base = 255 - lane * 8;
    unsigned int hb[8];
    unsigned int s = 0;
#pragma unroll
    for (int q = 0; q < 8; q++) { hb[q] = hist[base - q]; s += hb[q]; }
    unsigned int incl = s;
#pragma unroll
    for (int d = 1; d < 32; d <<= 1) {
        unsigned int t = __shfl_up_sync(0xFFFFFFFFu, incl, d);
        if (lane >= d) incl += t;
    }
    unsigned int excl = incl - s;
    if (excl < (unsigned)kk && (unsigned)kk <= incl) {
        unsigned int acc = excl;
#pragma unroll
        for (int q = 0; q < 8; q++) {
            if (acc + hb[q] >= (unsigned)kk) {
                *sel_prefix = pfx | ((unsigned)(base - q) << shift);
                *sel_kr = kk - (int)acc;
                break;
            }
            acc += hb[q];
        }
    }
}

// ================= K0: mask + transpose + fp16-convert fc1 weights ============
__global__ void k_prep(const float* __restrict__ w, const float* __restrict__ m) {
    __shared__ float tile[32][33];
    int jb = blockIdx.x * 32;
    int nb = blockIdx.y * 32;
    int tx = threadIdx.x, ty = threadIdx.y;   // (32, 8)
#pragma unroll
    for (int r = 0; r < 32; r += 8) {
        int n = nb + ty + r;
        int j = jb + tx;
        float wv = w[n * CL + j];
        float mv = m[n * CL + j];
        tile[ty + r][tx] = (mv < 0.5f) ? wv : 0.0f;
    }
    __syncthreads();
#pragma unroll
    for (int r = 0; r < 32; r += 8) {
        int j = jb + ty + r;
        int n = nb + tx;
        g_Wh[j * NFC + n] = __float2half(tile[tx][ty + r]);
    }
}

// ================= K1: fused conv + pool + kwinners(400/9216) =================
#define T1 288

__global__ void __launch_bounds__(T1) k_conv_pool_kw(
    const float* __restrict__ x, const float* __restrict__ cw,
    const float* __restrict__ cb, const float* __restrict__ duty)
{
    __shared__ unsigned int s_keys[CL];    // 36 KB
    __shared__ float img[IMH * IMW];
    __shared__ float wts[C1 * 25];
    __shared__ float bias[C1];
    __shared__ float boost[C1];
    __shared__ unsigned int hist[256];
    __shared__ int s_wsum[16];
    __shared__ unsigned int sel_prefix;
    __shared__ int sel_kr;
    __shared__ int sel_total;

    const int tid = threadIdx.x;
    const int b   = blockIdx.x;
    const int lane = tid & 31, wrp = tid >> 5;

    const float* xb = x + b * (IMH * IMW);
    for (int i = tid; i < IMH * IMW; i += T1) img[i] = xb[i];
    for (int i = tid; i < C1 * 25;   i += T1) wts[i] = cw[i];
    if (tid < C1) {
        bias[tid]  = cb[tid];
        boost[tid] = expf(400.0f / 9216.0f - duty[tid]);
    }
    __syncthreads();

    // ---- conv 5x5 + maxpool 2x2, scalar fp32, patch in registers ----
    {
        int pos = tid % POS;
        int cg  = tid / POS;
        int py = pos / PH, px = pos % PH;
        int r0 = py * 2, c0 = px * 2;
        float p[36];
#pragma unroll
        for (int u = 0; u < 6; u++)
#pragma unroll
            for (int v = 0; v < 6; v++)
                p[u * 6 + v] = img[(r0 + u) * IMW + (c0 + v)];
        int cbase = cg * 32;
        for (int cc = 0; cc < 32; cc++) {
            int c = cbase + cc;
            const float* wc = wts + c * 25;
            float s00 = 0.f, s01 = 0.f, s10 = 0.f, s11 = 0.f;
#pragma unroll
            for (int u = 0; u < 5; u++) {
#pragma unroll
                for (int v = 0; v < 5; v++) {
                    float wv = wc[u * 5 + v];
                    s00 = fmaf(p[u * 6 + v],     wv, s00);
                    s01 = fmaf(p[u * 6 + v + 1], wv, s01);
                    s10 = fmaf(p[u * 6 + 6 + v], wv, s10);
                    s11 = fmaf(p[u * 6 + 7 + v], wv, s11);
                }
            }
            float pv = fmaxf(fmaxf(s00, s01), fmaxf(s10, s11)) + bias[c];
            s_keys[c * POS + pos] = f2u(pv * boost[c]);
        }
    }
    __syncthreads();

    // ---- exact k-th largest via 4-pass radix select (warp-parallel bins) ----
    if (tid == 0) { sel_prefix = 0u; sel_kr = K1K; }
    __syncthreads();
    for (int shift = 24; shift >= 0; shift -= 8) {
        if (tid < 256) hist[tid] = 0u;
        __syncthreads();
        unsigned int pfx    = sel_prefix;
        int          kk     = sel_kr;
        unsigned int himask = (shift == 24) ? 0u : (0xFFFFFFFFu << (shift + 8));
        for (int i = tid; i < CL; i += T1) {
            unsigned int u = s_keys[i];
            if ((u & himask) == pfx) atomicAdd(&hist[(u >> shift) & 255], 1u);
        }
        __syncthreads();
        if (wrp == 0)
            warp_select_bin(hist, kk, lane, shift, pfx, &sel_prefix, &sel_kr);
        __syncthreads();
    }
    unsigned int thr = sel_prefix;

    // ---- deterministic compaction (fused pair write, stride i<<7) ----
    int mycnt = 0;
    for (int i = tid; i < CL; i += T1)
        if (s_keys[i] >= thr) mycnt++;

    int v = mycnt;
#pragma unroll
    for (int d = 1; d < 32; d <<= 1) {
        int t = __shfl_up_sync(0xFFFFFFFFu, v, d);
        if (lane >= d) v += t;
    }
    if (lane == 31) s_wsum[wrp] = v;
    __syncthreads();
    if (tid == 0) {
        int a = 0;
        for (int w = 0; w < T1 / 32; w++) { int t = s_wsum[w]; s_wsum[w] = a; a += t; }
        sel_total = a;
    }
    __syncthreads();
    int off = s_wsum[wrp] + v - mycnt;
    for (int i = tid; i < CL; i += T1) {
        unsigned int k = s_keys[i];
        if (k >= thr) {
            if (off < CAP) {
                g_pair[b * CAP + off] =
                    make_float2(u2f(k) / boost[i / POS],
                                __int_as_float(i << 7));   // i * (NFC/8)
            }
            off++;
        }
    }
    if (tid == 0) g_cnt[b] = sel_total > CAP ? CAP : sel_total;
}

// ================= K2: fp16 fc1 (uint4, 8 neurons/thread) + exact kwinners ====
#define T2 128

__global__ void __launch_bounds__(T2) k_fc_out(
    const float* __restrict__ fw,    const float* __restrict__ fmask,
    const float* __restrict__ fc1_b, const float* __restrict__ duty_fc,
    const float* __restrict__ w2,    const float* __restrict__ b2,
    float* __restrict__ out)
{
    __shared__ float2        s_pair[CAP];
    __shared__ float         s_h[NFC];
    __shared__ float         s_bst[NFC];
    __shared__ unsigned int  s_keys[NFC];
    __shared__ unsigned char s_flag[NFC];
    __shared__ unsigned int  hist[256];
    __shared__ unsigned int  sel_prefix;
    __shared__ int           sel_kr;
    __shared__ float         s_red[4][10];
    __shared__ float         s_logits[10];
    __shared__ float         s_lse;
    __shared__ float         s_Q[4];
    __shared__ int           s_ic[4];
    __shared__ int           s_ccnt;
    __shared__ int           s_cnd_n[CANDCAP];
    __shared__ unsigned int  s_cnd_k[CANDCAP];
    __shared__ unsigned char s_used[CANDCAP];

    const int tid  = threadIdx.x;
    const int b    = blockIdx.x;
    const int lane = tid & 31, wrp = tid >> 5;

    int cnt = g_cnt[b];
    float myQ = 0.f;
    for (int i = tid; i < cnt; i += T2) {
        float2 pr = g_pair[b * CAP + i];
        s_pair[i] = pr;
        myQ = fmaf(pr.x, pr.x, myQ);
    }
#pragma unroll
    for (int d = 16; d > 0; d >>= 1) myQ += __shfl_down_sync(0xFFFFFFFFu, myQ, d);
    if (lane == 0) s_Q[wrp] = myQ;
    if (tid == 0) s_ccnt = 0;
    __syncthreads();
    float Q2 = s_Q[0] + s_Q[1] + s_Q[2] + s_Q[3];

    // ---- fp16 sparse accumulate: LDG.128, 8 neurons per thread ----
    float a0 = 0.f, a1 = 0.f, a2 = 0.f, a3 = 0.f;
    float a4 = 0.f, a5 = 0.f, a6 = 0.f, a7 = 0.f;
    const uint4* __restrict__ W16 = (const uint4*)g_Wh;  // 16B = 8 halfs
#pragma unroll 8
    for (int e = 0; e < cnt; e++) {
        float2 pv = s_pair[e];
        int jn = __float_as_int(pv.y);           // i * 128
        uint4 wraw = __ldg(&W16[jn + tid]);
        float2 f01 = __half22float2(*(const __half2*)&wraw.x);
        float2 f23 = __half22float2(*(const __half2*)&wraw.y);
        float2 f45 = __half22float2(*(const __half2*)&wraw.z);
        float2 f67 = __half22float2(*(const __half2*)&wraw.w);
        a0 = fmaf(pv.x, f01.x, a0);
        a1 = fmaf(pv.x, f01.y, a1);
        a2 = fmaf(pv.x, f23.x, a2);
        a3 = fmaf(pv.x, f23.y, a3);
        a4 = fmaf(pv.x, f45.x, a4);
        a5 = fmaf(pv.x, f45.y, a5);
        a6 = fmaf(pv.x, f67.x, a6);
        a7 = fmaf(pv.x, f67.y, a7);
    }

    const float kdn = 100.0f / 1024.0f;
    {
        float av[8] = {a0, a1, a2, a3, a4, a5, a6, a7};
        int n = tid * 8;
#pragma unroll
        for (int q = 0; q < 8; q++) {
            float h = av[q] + fc1_b[n + q];
            float bo = expf(kdn - duty_fc[n + q]);
            s_h[n + q]    = h;
            s_bst[n + q]  = bo;
            s_keys[n + q] = f2u(h * bo);
        }
    }
    __syncthreads();

    // ---- radix select approx rank-100 threshold ----
    if (tid == 0) { sel_prefix = 0u; sel_kr = KFC; }
    __syncthreads();
    for (int shift = 24; shift >= 0; shift -= 8) {
        hist[tid] = 0u;
        hist[tid + 128] = 0u;
        __syncthreads();
        unsigned int pfx    = sel_prefix;
        int          kk     = sel_kr;
        unsigned int himask = (shift == 24) ? 0u : (0xFFFFFFFFu << (shift + 8));
#pragma unroll
        for (int q = 0; q < 8; q++) {
            unsigned int u = s_keys[tid * 8 + q];
            if ((u & himask) == pfx) atomicAdd(&hist[(u >> shift) & 255], 1u);
        }
        __syncthreads();
        if (wrp == 0)
            warp_select_bin(hist, kk, lane, shift, pfx, &sel_prefix, &sel_kr);
        __syncthreads();
    }
    const unsigned int thr = sel_prefix;
    const float tval = __uint_as_float((thr & 0x80000000u) ? (thr & 0x7fffffffu) : ~thr);
    const float mband = 4.0e-3f * sqrtf(Q2 * 6.0e-5f) + 1.0e-4f;

    // ---- flag pass ----
#pragma unroll
    for (int q = 0; q < 8; q++) {
        int n = tid * 8 + q;
        float hb = s_h[n] * s_bst[n];
        unsigned char fl = (s_keys[n] >= thr) ? 1 : 0;
        if (fabsf(hb - tval) <= mband) {
            fl = 2;
            int pos = atomicAdd(&s_ccnt, 1);
            if (pos < CANDCAP) s_cnd_n[pos] = n;
        }
        s_flag[n] = fl;
    }
    __syncthreads();
    int ccnt = min(s_ccnt, CANDCAP);

    // ---- exact fp32 recompute for candidates from ORIGINAL weights+mask ----
    for (int c = wrp; c < ccnt; c += 4) {
        int n = s_cnd_n[c];
        const float* wrow = fw    + (size_t)n * CL;
        const float* mrow = fmask + (size_t)n * CL;
        float part = 0.f;
        for (int ee = lane; ee < cnt; ee += 32) {
            float2 pr = s_pair[ee];
            int j = __float_as_int(pr.y) >> 7;
            float wv = __ldg(&wrow[j]);
            float mv = __ldg(&mrow[j]);
            if (mv < 0.5f) part = fmaf(pr.x, wv, part);
        }
#pragma unroll
        for (int d = 16; d > 0; d >>= 1)
            part += __shfl_down_sync(0xFFFFFFFFu, part, d);
        if (lane == 0) {
            float h = part + fc1_b[n];
            s_h[n] = h;
            s_cnd_k[c] = f2u(h * s_bst[n]);
        }
    }
    __syncthreads();

    // ---- count definite-ins, resolve candidates exactly ----
    {
        int myc = 0;
#pragma unroll
        for (int q = 0; q < 8; q++) myc += (s_flag[tid * 8 + q] == 1);
#pragma unroll
        for (int d = 16; d > 0; d >>= 1) myc += __shfl_down_sync(0xFFFFFFFFu, myc, d);
        if (lane == 0) s_ic[wrp] = myc;
    }
    __syncthreads();
    if (tid == 0) {
        int ic = s_ic[0] + s_ic[1] + s_ic[2] + s_ic[3];
        int r = KFC - ic;
        if (r < 1) r = 1;
        if (r > ccnt) r = ccnt;
        for (int c = 0; c < ccnt; c++) s_used[c] = 0;
        unsigned int kth = 0u;
        for (int s = 0; s < r; s++) {
            int bi = -1; unsigned int bk = 0u;
            for (int c = 0; c < ccnt; c++)
                if (!s_used[c] && (bi < 0 || s_cnd_k[c] > bk)) { bi = c; bk = s_cnd_k[c]; }
            s_used[bi] = 1; kth = bk;
        }
        for (int c = 0; c < ccnt; c++)
            s_flag[s_cnd_n[c]] = (s_cnd_k[c] >= kth) ? 1 : 0;
    }
    __syncthreads();

    // ---- fc2 over winners ----
    float part[10];
#pragma unroll
    for (int c = 0; c < 10; c++) part[c] = 0.f;
#pragma unroll
    for (int q = 0; q < 8; q++) {
        int n = tid * 8 + q;
        unsigned char fl = s_flag[n];
        bool win = (fl == 1) || (fl == 2 && s_keys[n] >= thr);
        if (win) {
            float hv = s_h[n];
#pragma unroll
            for (int c = 0; c < 10; c++)
                part[c] = fmaf(hv, w2[c * NFC + n], part[c]);
        }
    }
#pragma unroll
    for (int c = 0; c < 10; c++) {
        float pv = part[c];
#pragma unroll
        for (int d = 16; d > 0; d >>= 1)
            pv += __shfl_down_sync(0xFFFFFFFFu, pv, d);
        if (lane == 0) s_red[wrp][c] = pv;
    }
    __syncthreads();
    if (tid < 10) {
        float s = s_red[0][tid] + s_red[1][tid] + s_red[2][tid] + s_red[3][tid];
        s_logits[tid] = s + b2[tid];
    }
    __syncthreads();
    if (tid == 0) {
        float mx = s_logits[0];
        for (int c = 1; c < 10; c++) mx = fmaxf(mx, s_logits[c]);
        float se = 0.f;
        for (int c = 0; c < 10; c++) se += expf(s_logits[c] - mx);
        s_lse = mx + logf(se);
    }
    __syncthreads();
    if (tid < 10) out[b * 10 + tid] = s_logits[tid] - s_lse;
}

// ================= launch =================
extern "C" void kernel_launch(void* const* d_in, const int* in_sizes, int n_in,
                              void* d_out, int out_size)
{
    const float* x        = (const float*)d_in[0];
    const float* c1_w     = (const float*)d_in[1];
    const float* c1_b     = (const float*)d_in[2];
    const float* duty_cnn = (const float*)d_in[3];
    const float* fc1_w    = (const float*)d_in[4];
    const float* fc1_mask = (const float*)d_in[5];
    const float* fc1_b    = (const float*)d_in[6];
    const float* duty_fc  = (const float*)d_in[7];
    const float* fc2_w    = (const float*)d_in[8];
    const float* fc2_b    = (const float*)d_in[9];
    float* out = (float*)d_out;

    k_prep<<<dim3(CL / 32, NFC / 32), dim3(32, 8)>>>(fc1_w, fc1_mask);
    k_conv_pool_kw<<<BATCH, T1>>>(x, c1_w, c1_b, duty_cnn);
    k_fc_out<<<BATCH, T2>>>(fc1_w, fc1_mask, fc1_b, duty_fc, fc2_w, fc2_b, out);
}